// round 9
// baseline (speedup 1.0000x reference)
#include <cuda_runtime.h>
#include <cuda_bf16.h>
#include <cstdint>

// Problem constants (fixed shapes for this problem)
#define B_   4
#define L_   2048
#define H_   8
#define D_   64
#define SK   40      // sample_k = 5*ceil(ln(2048)) = 40
#define U_   40      // u = min(40, 2048)
#define BH   32      // B_*H_
#define SCALE 0.125f // 1/sqrt(64)
#define NT3  8       // k-tiles for context partials

// Scratch (device globals — no allocation allowed)
__device__ float g_M[BH * L_];                 // 256 KB
__device__ int   g_top[BH * U_];               // 5 KB
__device__ float g_S[(size_t)BH * U_ * L_];    // 10.5 MB: scores -> normalized suffix attn
__device__ float g_C[NT3 * BH * U_ * D_];      // 2.6 MB: context partials

// ---------------------------------------------------------------------------
// K1: M[b,h,q] = max_s(Q.K_sample) - sum_s(Q.K_sample)/L
// one warp per (b,h,q); lane covers 2 dims (float2); coalesced 256B K gathers
// ---------------------------------------------------------------------------
__global__ __launch_bounds__(256) void k1_sample(const float* __restrict__ Q,
                                                 const float* __restrict__ K,
                                                 const int*   __restrict__ idx) {
    int wid  = (blockIdx.x * blockDim.x + threadIdx.x) >> 5;  // [0, BH*L)
    int lane = threadIdx.x & 31;
    int q  = wid & (L_ - 1);
    int bh = wid >> 11;
    int b = bh >> 3, h = bh & 7;

    const float2* qrow = (const float2*)(Q + ((size_t)(b * L_ + q) * H_ + h) * D_);
    float2 qv = qrow[lane];

    float mx = -1e30f, sm = 0.f;
    const int* ip = idx + q * SK;

#pragma unroll 4
    for (int s = 0; s < SK; s++) {
        int j = __ldg(ip + s);
        const float2* krow = (const float2*)(K + ((size_t)(b * L_ + j) * H_ + h) * D_);
        float2 kv = krow[lane];
        float p = qv.x * kv.x + qv.y * kv.y;
        p += __shfl_xor_sync(0xffffffffu, p, 16);
        p += __shfl_xor_sync(0xffffffffu, p, 8);
        p += __shfl_xor_sync(0xffffffffu, p, 4);
        p += __shfl_xor_sync(0xffffffffu, p, 2);
        p += __shfl_xor_sync(0xffffffffu, p, 1);
        mx = fmaxf(mx, p);
        sm += p;
    }
    if (lane == 0) g_M[bh * L_ + q] = mx - sm * (1.0f / (float)L_);
}

// ---------------------------------------------------------------------------
// K2: stable top-40 per (b,h): descending value, ties -> lower index
// (matches jax.lax.top_k ordering). One block per (b,h).
// ---------------------------------------------------------------------------
__global__ __launch_bounds__(256) void k2_topk() {
    int bh  = blockIdx.x;
    int tid = threadIdx.x;
    __shared__ float sv[L_];
    __shared__ float rv[256];
    __shared__ int   ri[256];

    for (int i = tid; i < L_; i += 256) sv[i] = g_M[bh * L_ + i];
    __syncthreads();

    for (int t = 0; t < U_; t++) {
        float bv = -1e30f; int bi = L_;
        for (int i = tid; i < L_; i += 256) {
            float v = sv[i];
            if (v > bv || (v == bv && i < bi)) { bv = v; bi = i; }
        }
        rv[tid] = bv; ri[tid] = bi;
        __syncthreads();
        for (int off = 128; off > 0; off >>= 1) {
            if (tid < off) {
                float v2 = rv[tid + off]; int i2 = ri[tid + off];
                if (v2 > rv[tid] || (v2 == rv[tid] && i2 < ri[tid])) {
                    rv[tid] = v2; ri[tid] = i2;
                }
            }
            __syncthreads();
        }
        if (tid == 0) { g_top[bh * U_ + t] = ri[0]; sv[ri[0]] = -1e30f; }
        __syncthreads();
    }
}

// ---------------------------------------------------------------------------
// K3a: scores[u,k] = (Q_reduce[u,:] . K[k,:]) * SCALE  -> g_S
// grid = (bh, 16 tiles of 128 k). 128 threads; thread owns one k, acc[40].
// ---------------------------------------------------------------------------
__global__ __launch_bounds__(128) void k3a_scores(const float* __restrict__ Q,
                                                  const float* __restrict__ K) {
    int bh   = blockIdx.x >> 4;
    int tile = blockIdx.x & 15;
    int b = bh >> 3, h = bh & 7;
    int tid = threadIdx.x;

    __shared__ float Qs[U_ * D_];       // 10 KB
    __shared__ float Ks[128 * 65];      // 33 KB, pad 65 -> conflict-free

    for (int i = tid; i < U_ * D_; i += 128) {
        int u = i >> 6, d = i & 63;
        int qi = g_top[bh * U_ + u];
        Qs[i] = Q[((size_t)(b * L_ + qi) * H_ + h) * D_ + d];
    }
    int k0 = tile * 128;
    for (int i = tid; i < 128 * D_; i += 128) {
        int kk = i >> 6, d = i & 63;
        Ks[kk * 65 + d] = K[((size_t)(b * L_ + k0 + kk) * H_ + h) * D_ + d];
    }
    __syncthreads();

    float acc[U_];
#pragma unroll
    for (int u = 0; u < U_; u++) acc[u] = 0.f;

    int kk = tid;
    for (int d = 0; d < D_; d++) {
        float kd = Ks[kk * 65 + d];
#pragma unroll
        for (int u = 0; u < U_; u++) acc[u] += kd * Qs[u * 64 + d];
    }
#pragma unroll
    for (int u = 0; u < U_; u++)
        g_S[((size_t)(bh * U_ + u)) * L_ + k0 + kk] = acc[u] * SCALE;
}

// ---------------------------------------------------------------------------
// K3b: per row (bh,u): softmax + suffix-sum, normalized, in place.
// S[k] = sum_{k'>=k} exp(s[k']-max) / Z.   1280 blocks, 256 threads.
// ---------------------------------------------------------------------------
__global__ __launch_bounds__(256) void k3b_scan() {
    int row = blockIdx.x;              // bh*U_ + u
    int tid = threadIdx.x;
    __shared__ float buf[L_];          // 8 KB
    __shared__ float red[256];

    float* src = g_S + (size_t)row * L_;
    float m = -1e30f;
    for (int i = tid; i < L_; i += 256) { float v = src[i]; buf[i] = v; m = fmaxf(m, v); }
    red[tid] = m; __syncthreads();
    for (int off = 128; off > 0; off >>= 1) {
        if (tid < off) red[tid] = fmaxf(red[tid], red[tid + off]);
        __syncthreads();
    }
    float rowmax = red[0];
    __syncthreads();

    // exp + local suffix within chunk of 8
    int base = tid * 8;
    float acc = 0.f;
#pragma unroll
    for (int j = 7; j >= 0; j--) {
        float e = __expf(buf[base + j] - rowmax);
        acc += e;
        buf[base + j] = acc;
    }
    red[tid] = acc; __syncthreads();

    // inclusive suffix scan of chunk sums (Hillis-Steele toward higher index)
    for (int off = 1; off < 256; off <<= 1) {
        float v = (tid + off < 256) ? red[tid + off] : 0.f;
        __syncthreads();
        red[tid] += v;
        __syncthreads();
    }
    float total  = red[0];
    float addoff = (tid < 255) ? red[tid + 1] : 0.f;
    float invZ   = 1.0f / total;

#pragma unroll
    for (int j = 0; j < 8; j++) buf[base + j] = (buf[base + j] + addoff) * invZ;
    __syncthreads();
    for (int i = tid; i < L_; i += 256) src[i] = buf[i];
}

// ---------------------------------------------------------------------------
// K3c: context partials: C_part[tile] = S[:, ktile] @ V[ktile, :]
// grid = (bh, 8 tiles of 256 k), looping 4 chunks of 64. Deterministic.
// ---------------------------------------------------------------------------
__global__ __launch_bounds__(256) void k3c_ctx(const float* __restrict__ V) {
    int bh   = blockIdx.x >> 3;
    int tile = blockIdx.x & 7;
    int b = bh >> 3, h = bh & 7;
    int tid = threadIdx.x;

    __shared__ float Vs[64 * 64];   // 16 KB
    __shared__ float Ss[U_ * 64];   // 10 KB

    int d  = tid & 63;
    int ug = tid >> 6;              // 0..3, constant within warp
    float acc[10];
#pragma unroll
    for (int r = 0; r < 10; r++) acc[r] = 0.f;

    for (int c = 0; c < 4; c++) {
        int k0 = tile * 256 + c * 64;
        __syncthreads();
        for (int i = tid; i < 64 * 64; i += 256) {
            int kk = i >> 6, dd = i & 63;
            Vs[i] = V[((size_t)(b * L_ + k0 + kk) * H_ + h) * D_ + dd];
        }
        for (int i = tid; i < U_ * 64; i += 256) {
            int u = i >> 6, kk = i & 63;
            Ss[i] = g_S[((size_t)(bh * U_ + u)) * L_ + k0 + kk];
        }
        __syncthreads();
        for (int k = 0; k < 64; k++) {
            float v = Vs[k * 64 + d];
#pragma unroll
            for (int r = 0; r < 10; r++)
                acc[r] += Ss[(r * 4 + ug) * 64 + k] * v;   // broadcast LDS
        }
    }
#pragma unroll
    for (int r = 0; r < 10; r++) {
        int u = r * 4 + ug;
        g_C[(size_t)tile * (BH * U_ * D_) + (bh * U_ + u) * D_ + d] = acc[r];
    }
}

// ---------------------------------------------------------------------------
// K3r: reduce partials -> out (writes every element; no memset needed)
// ---------------------------------------------------------------------------
__global__ __launch_bounds__(256) void k3r_reduce(float* __restrict__ out) {
    int i = blockIdx.x * 256 + threadIdx.x;   // < BH*U_*D_ = 81920
    float s = 0.f;
#pragma unroll
    for (int t = 0; t < NT3; t++) s += g_C[(size_t)t * (BH * U_ * D_) + i];
    out[i] = s;
}

// ---------------------------------------------------------------------------
extern "C" void kernel_launch(void* const* d_in, const int* in_sizes, int n_in,
                              void* d_out, int out_size) {
    const float* Q   = (const float*)d_in[0];
    const float* K   = (const float*)d_in[1];
    const float* V   = (const float*)d_in[2];
    const int*   idx = (const int*)d_in[3];
    float* out = (float*)d_out;

    // K1: 65536 warps -> 8192 blocks of 256 threads
    k1_sample<<<(BH * L_ * 32) / 256, 256>>>(Q, K, idx);
    // K2: one block per (b,h)
    k2_topk<<<BH, 256>>>();
    // K3a: 32 bh x 16 k-tiles
    k3a_scores<<<BH * 16, 128>>>(Q, K);
    // K3b: one block per (bh, u) row
    k3b_scan<<<BH * U_, 256>>>();
    // K3c: 32 bh x 8 k-tiles
    k3c_ctx<<<BH * NT3, 256>>>(V);
    // K3r: final reduce into d_out
    k3r_reduce<<<(BH * U_ * D_) / 256, 256>>>(out);
}

// round 10
// speedup vs baseline: 1.0013x; 1.0013x over previous
#include <cuda_runtime.h>
#include <cuda_bf16.h>
#include <cstdint>

// Problem constants (fixed shapes for this problem)
#define B_   4
#define L_   2048
#define H_   8
#define D_   64
#define SK   40      // sample_k = 5*ceil(ln(2048)) = 40
#define U_   40      // u = min(40, 2048)
#define BH   32      // B_*H_
#define SCALE 0.125f // 1/sqrt(64)
#define NT3  8       // k-tiles for context partials

// Scratch (device globals — no allocation allowed)
__device__ float g_M[BH * L_];                 // 256 KB
__device__ int   g_top[BH * U_];               // 5 KB
__device__ float g_S[(size_t)BH * U_ * L_];    // 10.5 MB: scores -> normalized suffix attn
__device__ float g_C[NT3 * BH * U_ * D_];      // 2.6 MB: context partials

// ---------------------------------------------------------------------------
// K1: M[b,h,q] = max_s(Q.K_sample) - sum_s(Q.K_sample)/L
// one warp per (b,h,q); lane covers 2 dims (float2); coalesced 256B K gathers
// ---------------------------------------------------------------------------
__global__ __launch_bounds__(256) void k1_sample(const float* __restrict__ Q,
                                                 const float* __restrict__ K,
                                                 const int*   __restrict__ idx) {
    int wid  = (blockIdx.x * blockDim.x + threadIdx.x) >> 5;  // [0, BH*L)
    int lane = threadIdx.x & 31;
    int q  = wid & (L_ - 1);
    int bh = wid >> 11;
    int b = bh >> 3, h = bh & 7;

    const float2* qrow = (const float2*)(Q + ((size_t)(b * L_ + q) * H_ + h) * D_);
    float2 qv = qrow[lane];

    float mx = -1e30f, sm = 0.f;
    const int* ip = idx + q * SK;

#pragma unroll 4
    for (int s = 0; s < SK; s++) {
        int j = __ldg(ip + s);
        const float2* krow = (const float2*)(K + ((size_t)(b * L_ + j) * H_ + h) * D_);
        float2 kv = krow[lane];
        float p = qv.x * kv.x + qv.y * kv.y;
        p += __shfl_xor_sync(0xffffffffu, p, 16);
        p += __shfl_xor_sync(0xffffffffu, p, 8);
        p += __shfl_xor_sync(0xffffffffu, p, 4);
        p += __shfl_xor_sync(0xffffffffu, p, 2);
        p += __shfl_xor_sync(0xffffffffu, p, 1);
        mx = fmaxf(mx, p);
        sm += p;
    }
    if (lane == 0) g_M[bh * L_ + q] = mx - sm * (1.0f / (float)L_);
}

// ---------------------------------------------------------------------------
// K2: stable top-40 per (b,h): descending value, ties -> lower index
// (matches jax.lax.top_k ordering). One block per (b,h).
// ---------------------------------------------------------------------------
__global__ __launch_bounds__(256) void k2_topk() {
    int bh  = blockIdx.x;
    int tid = threadIdx.x;
    __shared__ float sv[L_];
    __shared__ float rv[256];
    __shared__ int   ri[256];

    for (int i = tid; i < L_; i += 256) sv[i] = g_M[bh * L_ + i];
    __syncthreads();

    for (int t = 0; t < U_; t++) {
        float bv = -1e30f; int bi = L_;
        for (int i = tid; i < L_; i += 256) {
            float v = sv[i];
            if (v > bv || (v == bv && i < bi)) { bv = v; bi = i; }
        }
        rv[tid] = bv; ri[tid] = bi;
        __syncthreads();
        for (int off = 128; off > 0; off >>= 1) {
            if (tid < off) {
                float v2 = rv[tid + off]; int i2 = ri[tid + off];
                if (v2 > rv[tid] || (v2 == rv[tid] && i2 < ri[tid])) {
                    rv[tid] = v2; ri[tid] = i2;
                }
            }
            __syncthreads();
        }
        if (tid == 0) { g_top[bh * U_ + t] = ri[0]; sv[ri[0]] = -1e30f; }
        __syncthreads();
    }
}

// ---------------------------------------------------------------------------
// K3a: scores[u,k] = (Q_reduce[u,:] . K[k,:]) * SCALE  -> g_S
// grid = (bh, 16 tiles of 128 k). 128 threads; thread owns one k, acc[40].
// ---------------------------------------------------------------------------
__global__ __launch_bounds__(128) void k3a_scores(const float* __restrict__ Q,
                                                  const float* __restrict__ K) {
    int bh   = blockIdx.x >> 4;
    int tile = blockIdx.x & 15;
    int b = bh >> 3, h = bh & 7;
    int tid = threadIdx.x;

    __shared__ float Qs[U_ * D_];       // 10 KB
    __shared__ float Ks[128 * 65];      // 33 KB, pad 65 -> conflict-free

    for (int i = tid; i < U_ * D_; i += 128) {
        int u = i >> 6, d = i & 63;
        int qi = g_top[bh * U_ + u];
        Qs[i] = Q[((size_t)(b * L_ + qi) * H_ + h) * D_ + d];
    }
    int k0 = tile * 128;
    for (int i = tid; i < 128 * D_; i += 128) {
        int kk = i >> 6, d = i & 63;
        Ks[kk * 65 + d] = K[((size_t)(b * L_ + k0 + kk) * H_ + h) * D_ + d];
    }
    __syncthreads();

    float acc[U_];
#pragma unroll
    for (int u = 0; u < U_; u++) acc[u] = 0.f;

    int kk = tid;
    for (int d = 0; d < D_; d++) {
        float kd = Ks[kk * 65 + d];
#pragma unroll
        for (int u = 0; u < U_; u++) acc[u] += kd * Qs[u * 64 + d];
    }
#pragma unroll
    for (int u = 0; u < U_; u++)
        g_S[((size_t)(bh * U_ + u)) * L_ + k0 + kk] = acc[u] * SCALE;
}

// ---------------------------------------------------------------------------
// K3b: per row (bh,u): softmax + suffix-sum, normalized, in place.
// S[k] = sum_{k'>=k} exp(s[k']-max) / Z.   1280 blocks, 256 threads.
// ---------------------------------------------------------------------------
__global__ __launch_bounds__(256) void k3b_scan() {
    int row = blockIdx.x;              // bh*U_ + u
    int tid = threadIdx.x;
    __shared__ float buf[L_];          // 8 KB
    __shared__ float red[256];

    float* src = g_S + (size_t)row * L_;
    float m = -1e30f;
    for (int i = tid; i < L_; i += 256) { float v = src[i]; buf[i] = v; m = fmaxf(m, v); }
    red[tid] = m; __syncthreads();
    for (int off = 128; off > 0; off >>= 1) {
        if (tid < off) red[tid] = fmaxf(red[tid], red[tid + off]);
        __syncthreads();
    }
    float rowmax = red[0];
    __syncthreads();

    // exp + local suffix within chunk of 8
    int base = tid * 8;
    float acc = 0.f;
#pragma unroll
    for (int j = 7; j >= 0; j--) {
        float e = __expf(buf[base + j] - rowmax);
        acc += e;
        buf[base + j] = acc;
    }
    red[tid] = acc; __syncthreads();

    // inclusive suffix scan of chunk sums (Hillis-Steele toward higher index)
    for (int off = 1; off < 256; off <<= 1) {
        float v = (tid + off < 256) ? red[tid + off] : 0.f;
        __syncthreads();
        red[tid] += v;
        __syncthreads();
    }
    float total  = red[0];
    float addoff = (tid < 255) ? red[tid + 1] : 0.f;
    float invZ   = 1.0f / total;

#pragma unroll
    for (int j = 0; j < 8; j++) buf[base + j] = (buf[base + j] + addoff) * invZ;
    __syncthreads();
    for (int i = tid; i < L_; i += 256) src[i] = buf[i];
}

// ---------------------------------------------------------------------------
// K3c: context partials: C_part[tile] = S[:, ktile] @ V[ktile, :]
// grid = (bh, 8 tiles of 256 k), looping 4 chunks of 64. Deterministic.
// ---------------------------------------------------------------------------
__global__ __launch_bounds__(256) void k3c_ctx(const float* __restrict__ V) {
    int bh   = blockIdx.x >> 3;
    int tile = blockIdx.x & 7;
    int b = bh >> 3, h = bh & 7;
    int tid = threadIdx.x;

    __shared__ float Vs[64 * 64];   // 16 KB
    __shared__ float Ss[U_ * 64];   // 10 KB

    int d  = tid & 63;
    int ug = tid >> 6;              // 0..3, constant within warp
    float acc[10];
#pragma unroll
    for (int r = 0; r < 10; r++) acc[r] = 0.f;

    for (int c = 0; c < 4; c++) {
        int k0 = tile * 256 + c * 64;
        __syncthreads();
        for (int i = tid; i < 64 * 64; i += 256) {
            int kk = i >> 6, dd = i & 63;
            Vs[i] = V[((size_t)(b * L_ + k0 + kk) * H_ + h) * D_ + dd];
        }
        for (int i = tid; i < U_ * 64; i += 256) {
            int u = i >> 6, kk = i & 63;
            Ss[i] = g_S[((size_t)(bh * U_ + u)) * L_ + k0 + kk];
        }
        __syncthreads();
        for (int k = 0; k < 64; k++) {
            float v = Vs[k * 64 + d];
#pragma unroll
            for (int r = 0; r < 10; r++)
                acc[r] += Ss[(r * 4 + ug) * 64 + k] * v;   // broadcast LDS
        }
    }
#pragma unroll
    for (int r = 0; r < 10; r++) {
        int u = r * 4 + ug;
        g_C[(size_t)tile * (BH * U_ * D_) + (bh * U_ + u) * D_ + d] = acc[r];
    }
}

// ---------------------------------------------------------------------------
// K3r: reduce partials -> out (writes every element; no memset needed)
// ---------------------------------------------------------------------------
__global__ __launch_bounds__(256) void k3r_reduce(float* __restrict__ out) {
    int i = blockIdx.x * 256 + threadIdx.x;   // < BH*U_*D_ = 81920
    float s = 0.f;
#pragma unroll
    for (int t = 0; t < NT3; t++) s += g_C[(size_t)t * (BH * U_ * D_) + i];
    out[i] = s;
}

// ---------------------------------------------------------------------------
extern "C" void kernel_launch(void* const* d_in, const int* in_sizes, int n_in,
                              void* d_out, int out_size) {
    const float* Q   = (const float*)d_in[0];
    const float* K   = (const float*)d_in[1];
    const float* V   = (const float*)d_in[2];
    const int*   idx = (const int*)d_in[3];
    float* out = (float*)d_out;

    // K1: 65536 warps -> 8192 blocks of 256 threads
    k1_sample<<<(BH * L_ * 32) / 256, 256>>>(Q, K, idx);
    // K2: one block per (b,h)
    k2_topk<<<BH, 256>>>();
    // K3a: 32 bh x 16 k-tiles
    k3a_scores<<<BH * 16, 128>>>(Q, K);
    // K3b: one block per (bh, u) row
    k3b_scan<<<BH * U_, 256>>>();
    // K3c: 32 bh x 8 k-tiles
    k3c_ctx<<<BH * NT3, 256>>>(V);
    // K3r: final reduce into d_out
    k3r_reduce<<<(BH * U_ * D_) / 256, 256>>>(out);
}